// round 15
// baseline (speedup 1.0000x reference)
#include <cuda_runtime.h>
#include <cuda_bf16.h>
#include <cuda_fp16.h>
#include <cstdint>

#define N_NODES   20000
#define N_EDGES   640000
#define BASIS     128
#define NUM_GAUSS 64
#define HIDDEN    256
#define NUM_GRAPHS 256

// ---------------- scratch (device globals) ----------------
__device__ uint16_t g_dfeat16[(size_t)N_EDGES * BASIS]; // dst-sorted d_feat (fp16)
__device__ float    g_C[2][(size_t)N_NODES * BASIS];    // ping-pong node states
__device__ uint16_t g_Cch[(size_t)N_NODES * BASIS];     // per-iter node transform (fp16)
__device__ uint16_t g_Wh[BASIS * BASIS];                // fcW fp16
__device__ int      g_perm[N_EDGES];
__device__ int      g_srcp[N_EDGES];
__device__ int      g_dstp[N_EDGES];
__device__ int      g_cnt[N_NODES];
__device__ int      g_off[N_NODES + 1];
__device__ int      g_cur[N_NODES];

__device__ __forceinline__ float fast_tanh(float x) {        // readout
    float xc = fminf(fmaxf(x, -9.0f), 9.0f);
    float e  = __expf(2.0f * xc);
    return __fdividef(e - 1.0f, e + 1.0f);
}

__device__ __forceinline__ float tanh_approx(float x) {      // edge kernel
    float y;
    asm("tanh.approx.f32 %0, %1;" : "=f"(y) : "f"(x));
    return y;
}

__device__ __forceinline__ uint2 f4_to_h4(float4 o) {
    uint32_t a, b;
    asm("cvt.rn.f16x2.f32 %0, %1, %2;" : "=r"(a) : "f"(o.y), "f"(o.x));
    asm("cvt.rn.f16x2.f32 %0, %1, %2;" : "=r"(b) : "f"(o.w), "f"(o.z));
    return make_uint2(a, b);
}

#define MMA_F16(D, a0, a1, a2, a3, b0, b1)                                     \
    asm volatile("mma.sync.aligned.m16n8k16.row.col.f32.f16.f16.f32 "          \
                 "{%0,%1,%2,%3}, {%4,%5,%6,%7}, {%8,%9}, {%0,%1,%2,%3};"       \
                 : "+f"((D)[0]), "+f"((D)[1]), "+f"((D)[2]), "+f"((D)[3])      \
                 : "r"(a0), "r"(a1), "r"(a2), "r"(a3), "r"(b0), "r"(b1))

#define LDSM_X4(r0, r1, r2, r3, addr)                                          \
    asm volatile("ldmatrix.sync.aligned.m8n8.x4.shared.b16 {%0,%1,%2,%3}, [%4];" \
                 : "=r"(r0), "=r"(r1), "=r"(r2), "=r"(r3) : "r"(addr))

#define LDSM_X2(r0, r1, addr)                                                  \
    asm volatile("ldmatrix.sync.aligned.m8n8.x2.shared.b16 {%0,%1}, [%2];"     \
                 : "=r"(r0), "=r"(r1) : "r"(addr))

// ---------------- K0: zero output ----------------
__global__ void k_zero(float* __restrict__ out) {
    ((float4*)out)[threadIdx.x] = make_float4(0.f, 0.f, 0.f, 0.f);
}

// ---------------- K1: C0 = embed[Z] ----------------
__global__ __launch_bounds__(256) void k_init(const int* __restrict__ Z,
                                              const float* __restrict__ embed) {
    int idx = blockIdx.x * 256 + threadIdx.x;
    int v = idx >> 5, c4 = idx & 31;
    float4 val = ((const float4*)embed)[(size_t)Z[v] * 32 + c4];
    ((float4*)g_C[0])[idx] = val;
}

// ---------------- sort-by-dst pipeline (one-time) ----------------
__global__ __launch_bounds__(256) void k_clear() {
    int i = blockIdx.x * 256 + threadIdx.x;
    if (i < N_NODES) g_cnt[i] = 0;
}

__global__ __launch_bounds__(256) void k_hist(const int* __restrict__ edge_index) {
    int e = blockIdx.x * 256 + threadIdx.x;
    if (e < N_EDGES) atomicAdd(&g_cnt[edge_index[N_EDGES + e]], 1);
}

__global__ __launch_bounds__(1024) void k_scan() {
    __shared__ int sdata[1024];
    int t = threadIdx.x;
    const int PER = 20;
    int base = t * PER;
    int v[PER]; int s = 0;
#pragma unroll
    for (int j = 0; j < PER; j++) {
        int i = base + j;
        v[j] = (i < N_NODES) ? g_cnt[i] : 0;
        s += v[j];
    }
    sdata[t] = s;
    __syncthreads();
    for (int off = 1; off < 1024; off <<= 1) {
        int y = (t >= off) ? sdata[t - off] : 0;
        __syncthreads();
        sdata[t] += y;
        __syncthreads();
    }
    int run = sdata[t] - s;
#pragma unroll
    for (int j = 0; j < PER; j++) {
        int i = base + j;
        if (i < N_NODES) { g_off[i] = run; g_cur[i] = run; run += v[j]; }
    }
    if (t == 1023) g_off[N_NODES] = run;
}

__global__ __launch_bounds__(256) void k_scatter(const int* __restrict__ edge_index) {
    int e = blockIdx.x * 256 + threadIdx.x;
    if (e < N_EDGES) {
        int dst = edge_index[N_EDGES + e];
        int pos = atomicAdd(&g_cur[dst], 1);
        g_perm[pos] = e;
        g_srcp[pos] = edge_index[e];
        g_dstp[pos] = dst;
    }
}

__global__ __launch_bounds__(256) void k_wsplit(const float* __restrict__ fcW) {
    for (int i = blockIdx.x * 256 + threadIdx.x; i < BASIS * BASIS; i += gridDim.x * 256) {
        __half h = __float2half_rn(fcW[i]);
        g_Wh[i] = __half_as_ushort(h);
    }
}

// ---------------- K2: d_feat (dst-sorted, fp16) = edge_attr[perm]@dfW.T + dfb --
__global__ __launch_bounds__(256) void k_dfeat(const float* __restrict__ edge_attr,
                                               const float* __restrict__ dfW,
                                               const float* __restrict__ dfb) {
    extern __shared__ float sm[];
    float* sW = sm;                  // [128][64]
    float* sA = sm + 128 * 64;       // [64][68]
    float* sB = sA + 64 * 68;        // [128]
    int*   sPerm = (int*)(sB + 128); // [64]
    int t = threadIdx.x;
    int e0 = blockIdx.x * 64;

    if (t < 64) sPerm[t] = g_perm[e0 + t];
    __syncthreads();

    for (int i = t; i < 2048; i += 256)
        ((float4*)sW)[i] = ((const float4*)dfW)[i];
    if (t < 128) sB[t] = dfb[t];
    for (int i = t; i < 64 * 16; i += 256) {
        int e = i >> 4, g4 = i & 15;
        float4 v = ((const float4*)edge_attr)[(size_t)sPerm[e] * 16 + g4];
        *(float4*)&sA[e * 68 + g4 * 4] = v;
    }
    __syncthreads();

    int tx = t & 7, ty = t >> 3;
    float acc[8][4];
#pragma unroll
    for (int ii = 0; ii < 8; ii++)
#pragma unroll
        for (int jj = 0; jj < 4; jj++) acc[ii][jj] = 0.f;

#pragma unroll 4
    for (int k = 0; k < 64; k += 4) {
        float4 av[8], wv[4];
#pragma unroll
        for (int ii = 0; ii < 8; ii++) av[ii] = *(float4*)&sA[(tx + 8 * ii) * 68 + k];
#pragma unroll
        for (int jj = 0; jj < 4; jj++) wv[jj] = *(float4*)&sW[(ty * 4 + jj) * 64 + k];
#pragma unroll
        for (int ii = 0; ii < 8; ii++)
#pragma unroll
            for (int jj = 0; jj < 4; jj++) {
                acc[ii][jj] = fmaf(av[ii].x, wv[jj].x, acc[ii][jj]);
                acc[ii][jj] = fmaf(av[ii].y, wv[jj].y, acc[ii][jj]);
                acc[ii][jj] = fmaf(av[ii].z, wv[jj].z, acc[ii][jj]);
                acc[ii][jj] = fmaf(av[ii].w, wv[jj].w, acc[ii][jj]);
            }
    }
    float4 bb = *(float4*)&sB[ty * 4];
#pragma unroll
    for (int ii = 0; ii < 8; ii++) {
        float4 o = make_float4(acc[ii][0] + bb.x, acc[ii][1] + bb.y,
                               acc[ii][2] + bb.z, acc[ii][3] + bb.w);
        ((uint2*)g_dfeat16)[(size_t)(e0 + tx + 8 * ii) * 32 + ty] = f4_to_h4(o);
    }
}

// ---------------- K3: Cc(fp16) = C@cfW.T + cfb ; C2 = C ----------------
__global__ __launch_bounds__(256) void k_node(const float* __restrict__ cfW,
                                              const float* __restrict__ cfb,
                                              int sb) {
    extern __shared__ float sm[];
    float* sW = sm;                  // [128][128]
    float* sC = sm + 16384;          // [32][132]
    float* sBb = sC + 32 * 132;      // [128]
    const float* C = g_C[sb];
    float* C2 = g_C[sb ^ 1];
    int t = threadIdx.x, n0 = blockIdx.x * 32;

    for (int i = t; i < 4096; i += 256)
        ((float4*)sW)[i] = ((const float4*)cfW)[i];
    if (t < 128) sBb[t] = cfb[t];
    for (int i = t; i < 32 * 32; i += 256) {
        int n = i >> 5, c4 = i & 31;
        *(float4*)&sC[n * 132 + c4 * 4] = ((const float4*)C)[(size_t)(n0 + n) * 32 + c4];
    }
    __syncthreads();

    int tx = t & 7, ty = t >> 3;
    float acc[4][4];
#pragma unroll
    for (int ii = 0; ii < 4; ii++)
#pragma unroll
        for (int jj = 0; jj < 4; jj++) acc[ii][jj] = 0.f;

#pragma unroll 4
    for (int k = 0; k < 128; k += 4) {
        float4 cv[4], wv[4];
#pragma unroll
        for (int ii = 0; ii < 4; ii++) cv[ii] = *(float4*)&sC[(tx + 8 * ii) * 132 + k];
#pragma unroll
        for (int jj = 0; jj < 4; jj++) wv[jj] = *(float4*)&sW[(ty * 4 + jj) * 128 + k];
#pragma unroll
        for (int ii = 0; ii < 4; ii++)
#pragma unroll
            for (int jj = 0; jj < 4; jj++) {
                acc[ii][jj] = fmaf(cv[ii].x, wv[jj].x, acc[ii][jj]);
                acc[ii][jj] = fmaf(cv[ii].y, wv[jj].y, acc[ii][jj]);
                acc[ii][jj] = fmaf(cv[ii].z, wv[jj].z, acc[ii][jj]);
                acc[ii][jj] = fmaf(cv[ii].w, wv[jj].w, acc[ii][jj]);
            }
    }
    float4 bb = *(float4*)&sBb[ty * 4];
#pragma unroll
    for (int ii = 0; ii < 4; ii++) {
        float4 o = make_float4(acc[ii][0] + bb.x, acc[ii][1] + bb.y,
                               acc[ii][2] + bb.z, acc[ii][3] + bb.w);
        ((uint2*)g_Cch)[(size_t)(n0 + tx + 8 * ii) * 32 + ty] = f4_to_h4(o);
    }
    for (int i = t; i < 32 * 32; i += 256) {
        int n = i >> 5, c4 = i & 31;
        ((float4*)C2)[(size_t)(n0 + n) * 32 + c4] = *(float4*)&sC[n * 132 + c4 * 4];
    }
}

// ---------------- K4 (hot): m = tanh((Cc[srcp]*d_feat)@fcW.T); C2[dst] += m -----
// All-fp16 operands. TE=128, 256 thr, ~71.7 KB smem.
// launch_bounds(256,2): 128-reg cap -> acc[64] fits with headroom, NO SPILLS.
#define TE  128
#define PB  136   // fp16 row stride
#define POH 68    // f32 staging stride (64 cols + pad)
__global__ __launch_bounds__(256, 2) void k_edge(int db) {
    extern __shared__ char smraw[];
    uint16_t* sW  = (uint16_t*)smraw;                // [128][136] fp16
    uint16_t* sP  = sW + 128 * PB;                   // [128][136] fp16
    int*      sSrc = (int*)(sP + TE * PB);           // [128]
    int*      sDst = sSrc + TE;                      // [128]
    float*    sOut = (float*)sP;                     // [128][68] f32, aliases sP
    float* C2 = g_C[db];
    int t = threadIdx.x, e0 = blockIdx.x * TE;

    // ---- phase 1: stage fp16 W; load src/dst ----
    for (int i = t; i < 2048; i += 256) {            // uint4 = 8 fp16
        int n = i >> 4, k8 = i & 15;
        *(uint4*)&sW[n * PB + k8 * 8] = ((const uint4*)g_Wh)[i];
    }
    if (t < TE) sSrc[t] = g_srcp[e0 + t];
    else        sDst[t - TE] = g_dstp[e0 + (t - TE)];
    __syncthreads();

    // ---- phase 2: P = h2(Cc[src]) * h2(d_feat)  (all fp16) ----
    for (int i = t; i < TE * 32; i += 256) {
        int e = i >> 5, c4 = i & 31;
        uint2 d2 = ((const uint2*)g_dfeat16)[(size_t)(e0 + e) * 32 + c4];
        uint2 c2 = ((const uint2*)g_Cch)[(size_t)sSrc[e] * 32 + c4];
        __half2 pa = __hmul2(*(__half2*)&d2.x, *(__half2*)&c2.x);
        __half2 pb = __hmul2(*(__half2*)&d2.y, *(__half2*)&c2.y);
        *(uint2*)&sP[e * PB + c4 * 4] =
            make_uint2(*(uint32_t*)&pa, *(uint32_t*)&pb);
    }
    __syncthreads();

    // ---- phase 3: fp16 GEMM  D[128x128] = P @ W^T, 8 warps 4m x 2n (32x64) ----
    const int lane = t & 31, wid = t >> 5;
    const int mbase = (wid >> 1) * 32;               // {0,32,64,96}
    const int nbase = (wid & 1) * 64;                // {0,64}
    const int aoff = (mbase + (lane & 15)) * PB + ((lane & 16) ? 8 : 0);
    const int boff = (nbase + (lane & 7)) * PB + ((lane & 8) ? 8 : 0);
    const uint32_t sPA = (uint32_t)__cvta_generic_to_shared(sP);
    const uint32_t sWA = (uint32_t)__cvta_generic_to_shared(sW);

    float acc[64];                                   // [mt2][nt8][4]
#pragma unroll
    for (int i = 0; i < 64; i++) acc[i] = 0.f;

#pragma unroll
    for (int kt = 0; kt < 8; kt++) {
        uint32_t a[2][4];
#pragma unroll
        for (int mt = 0; mt < 2; mt++) {
            uint32_t off = (uint32_t)(aoff + mt * 16 * PB + kt * 16) * 2;
            LDSM_X4(a[mt][0], a[mt][1], a[mt][2], a[mt][3], sPA + off);
        }
#pragma unroll
        for (int nt = 0; nt < 8; nt++) {
            uint32_t off = (uint32_t)(boff + nt * 8 * PB + kt * 16) * 2;
            uint32_t b0, b1;
            LDSM_X2(b0, b1, sWA + off);
#pragma unroll
            for (int mt = 0; mt < 2; mt++) {
                float* D = acc + (mt * 8 + nt) * 4;
                MMA_F16(D, a[mt][0], a[mt][1], a[mt][2], a[mt][3], b0, b1);
            }
        }
    }
    __syncthreads();                                 // all sP reads done

    // ---- phases 4+5: two column halves; sOut aliases sP ----
    const int grp = lane >> 2, t4 = lane & 3;
#pragma unroll
    for (int half = 0; half < 2; half++) {
        if ((nbase >> 6) == half) {                  // 4 warps own these 64 cols
#pragma unroll
            for (int mt = 0; mt < 2; mt++)
#pragma unroll
                for (int nt = 0; nt < 8; nt++) {
                    int m = mbase + mt * 16 + grp;
                    int n = nt * 8 + 2 * t4;
                    const float* D = acc + (mt * 8 + nt) * 4;
                    *(float2*)&sOut[m * POH + n] =
                        make_float2(tanh_approx(D[0]), tanh_approx(D[1]));
                    *(float2*)&sOut[(m + 8) * POH + n] =
                        make_float2(tanh_approx(D[2]), tanh_approx(D[3]));
                }
        }
        __syncthreads();
        // run-aggregated scatter for this half (dst-sorted rows)
        {
            int c4 = t & 15;                         // float4 col within half
            int r0 = (t >> 4) * 8;                   // 16 strips x 8 rows
            float4 a4 = make_float4(0.f, 0.f, 0.f, 0.f);
            int cur = sDst[r0];
#pragma unroll
            for (int j = 0; j < 8; j++) {
                int r = r0 + j;
                int d = sDst[r];
                if (d != cur) {
                    float* ptr = C2 + (size_t)cur * BASIS + half * 64 + c4 * 4;
                    asm volatile("red.global.add.v4.f32 [%0], {%1,%2,%3,%4};"
                                 :: "l"(ptr), "f"(a4.x), "f"(a4.y), "f"(a4.z), "f"(a4.w)
                                 : "memory");
                    a4 = make_float4(0.f, 0.f, 0.f, 0.f);
                    cur = d;
                }
                float4 v = *(float4*)&sOut[r * POH + c4 * 4];
                a4.x += v.x; a4.y += v.y; a4.z += v.z; a4.w += v.w;
            }
            float* ptr = C2 + (size_t)cur * BASIS + half * 64 + c4 * 4;
            asm volatile("red.global.add.v4.f32 [%0], {%1,%2,%3,%4};"
                         :: "l"(ptr), "f"(a4.x), "f"(a4.y), "f"(a4.z), "f"(a4.w)
                         : "memory");
        }
        if (half == 0) __syncthreads();              // before overwriting sOut
    }
}

// ---------------- K5: readout + pool ----------------
__global__ __launch_bounds__(256) void k_readout(const float* __restrict__ r1W,
                                                 const float* __restrict__ r1b,
                                                 const float* __restrict__ r2W,
                                                 const float* __restrict__ r2b,
                                                 const int* __restrict__ batch,
                                                 float* __restrict__ out, int sb) {
    extern __shared__ float sm[];
    float* sW1 = sm;                   // [256][128]
    float* sC  = sW1 + 32768;          // [32][132]
    float* sW2 = sC + 32 * 132;        // [4][256]
    float* sB1 = sW2 + 1024;           // [256]
    float* sAcc = sB1 + 256;           // [32][4]
    int*   sBat = (int*)(sAcc + 128);  // [32]
    const float* C = g_C[sb];
    int t = threadIdx.x, n0 = blockIdx.x * 32;

    for (int i = t; i < 8192; i += 256)
        ((float4*)sW1)[i] = ((const float4*)r1W)[i];
    if (t < 256) ((float4*)sW2)[t] = ((const float4*)r2W)[t];
    sB1[t] = r1b[t];
    if (t < 128) sAcc[t] = 0.f;
    if (t < 32)  sBat[t] = batch[n0 + t];
    for (int i = t; i < 32 * 32; i += 256) {
        int n = i >> 5, c4 = i & 31;
        *(float4*)&sC[n * 132 + c4 * 4] = ((const float4*)C)[(size_t)(n0 + n) * 32 + c4];
    }
    __syncthreads();

    int tx = t & 7, ty = t >> 3;
    float acc[4][8];
#pragma unroll
    for (int ii = 0; ii < 4; ii++)
#pragma unroll
        for (int jj = 0; jj < 8; jj++) acc[ii][jj] = 0.f;

#pragma unroll 2
    for (int c = 0; c < 128; c += 4) {
        float4 cv[4], wv[8];
#pragma unroll
        for (int ii = 0; ii < 4; ii++) cv[ii] = *(float4*)&sC[(tx + 8 * ii) * 132 + c];
#pragma unroll
        for (int jj = 0; jj < 8; jj++) wv[jj] = *(float4*)&sW1[(ty * 8 + jj) * 128 + c];
#pragma unroll
        for (int ii = 0; ii < 4; ii++)
#pragma unroll
            for (int jj = 0; jj < 8; jj++) {
                acc[ii][jj] = fmaf(cv[ii].x, wv[jj].x, acc[ii][jj]);
                acc[ii][jj] = fmaf(cv[ii].y, wv[jj].y, acc[ii][jj]);
                acc[ii][jj] = fmaf(cv[ii].z, wv[jj].z, acc[ii][jj]);
                acc[ii][jj] = fmaf(cv[ii].w, wv[jj].w, acc[ii][jj]);
            }
    }
    float po[4][4];
#pragma unroll
    for (int ii = 0; ii < 4; ii++)
#pragma unroll
        for (int o = 0; o < 4; o++) po[ii][o] = (ty == 0) ? r2b[o] : 0.f;
#pragma unroll
    for (int ii = 0; ii < 4; ii++)
#pragma unroll
        for (int jj = 0; jj < 8; jj++) {
            float h = fast_tanh(acc[ii][jj] + sB1[ty * 8 + jj]);
#pragma unroll
            for (int o = 0; o < 4; o++)
                po[ii][o] = fmaf(h, sW2[o * 256 + ty * 8 + jj], po[ii][o]);
        }
#pragma unroll
    for (int ii = 0; ii < 4; ii++)
#pragma unroll
        for (int o = 0; o < 4; o++)
            atomicAdd(&sAcc[(tx + 8 * ii) * 4 + o], po[ii][o]);
    __syncthreads();
    if (t < 128) {
        int n = t >> 2, o = t & 3;
        atomicAdd(&out[(size_t)sBat[n] * 4 + o], sAcc[t]);
    }
}

// ---------------- launch ----------------
extern "C" void kernel_launch(void* const* d_in, const int* in_sizes, int n_in,
                              void* d_out, int out_size) {
    const int*   Z         = (const int*)d_in[0];
    const int*   edge_index= (const int*)d_in[1];
    const float* edge_attr = (const float*)d_in[2];
    const int*   batch     = (const int*)d_in[3];
    const float* embed     = (const float*)d_in[4];
    const float* cfW       = (const float*)d_in[5];
    const float* cfb       = (const float*)d_in[6];
    const float* dfW       = (const float*)d_in[7];
    const float* dfb       = (const float*)d_in[8];
    const float* fcW       = (const float*)d_in[9];
    const float* r1W       = (const float*)d_in[10];
    const float* r1b       = (const float*)d_in[11];
    const float* r2W       = (const float*)d_in[12];
    const float* r2b       = (const float*)d_in[13];
    float* out = (float*)d_out;

    const int smK2 = (128 * 64 + 64 * 68 + 128) * 4 + 64 * 4;             // ~51 KB
    const int smK3 = (16384 + 32 * 132 + 128) * 4;                        // ~83 KB
    const int smK4 = (128 * PB + TE * PB) * 2 + 2 * TE * 4;               // ~71.7 KB
    const int smK5 = (32768 + 32 * 132 + 1024 + 256 + 128) * 4 + 32 * 4;  // ~154 KB

    cudaFuncSetAttribute(k_dfeat,   cudaFuncAttributeMaxDynamicSharedMemorySize, smK2);
    cudaFuncSetAttribute(k_node,    cudaFuncAttributeMaxDynamicSharedMemorySize, smK3);
    cudaFuncSetAttribute(k_edge,    cudaFuncAttributeMaxDynamicSharedMemorySize, smK4);
    cudaFuncSetAttribute(k_readout, cudaFuncAttributeMaxDynamicSharedMemorySize, smK5);

    k_zero<<<1, 256>>>(out);
    k_init<<<(N_NODES * 32) / 256, 256>>>(Z, embed);

    // one-time edge sort by dst + W fp16 conversion
    k_clear<<<(N_NODES + 255) / 256, 256>>>();
    k_hist<<<(N_EDGES + 255) / 256, 256>>>(edge_index);
    k_scan<<<1, 1024>>>();
    k_scatter<<<(N_EDGES + 255) / 256, 256>>>(edge_index);
    k_wsplit<<<64, 256>>>(fcW);

    k_dfeat<<<N_EDGES / 64, 256, smK2>>>(edge_attr, dfW, dfb);

    int sb = 0;
    for (int it = 0; it < 3; it++) {
        k_node<<<N_NODES / 32, 256, smK3>>>(cfW, cfb, sb);
        k_edge<<<N_EDGES / TE, 256, smK4>>>(sb ^ 1);
        sb ^= 1;
    }
    k_readout<<<N_NODES / 32, 256, smK5>>>(r1W, r1b, r2W, r2b, batch, out, sb);
}

// round 16
// speedup vs baseline: 1.1938x; 1.1938x over previous
#include <cuda_runtime.h>
#include <cuda_bf16.h>
#include <cuda_fp16.h>
#include <cstdint>

#define N_NODES   20000
#define N_EDGES   640000
#define BASIS     128
#define NUM_GAUSS 64
#define HIDDEN    256
#define NUM_GRAPHS 256

// ---------------- scratch (device globals) ----------------
__device__ uint16_t g_dfeat16[(size_t)N_EDGES * BASIS]; // dst-sorted d_feat (fp16)
__device__ float    g_C[2][(size_t)N_NODES * BASIS];    // ping-pong node states
__device__ uint16_t g_Cch[(size_t)N_NODES * BASIS];     // per-iter node transform (fp16)
__device__ uint16_t g_Wh[BASIS * BASIS];                // fcW fp16
__device__ int      g_perm[N_EDGES];
__device__ int      g_srcp[N_EDGES];
__device__ int      g_dstp[N_EDGES];
__device__ int      g_cnt[N_NODES];
__device__ int      g_off[N_NODES + 1];
__device__ int      g_cur[N_NODES];

__device__ __forceinline__ float fast_tanh(float x) {        // readout
    float xc = fminf(fmaxf(x, -9.0f), 9.0f);
    float e  = __expf(2.0f * xc);
    return __fdividef(e - 1.0f, e + 1.0f);
}

__device__ __forceinline__ float tanh_approx(float x) {      // edge kernel
    float y;
    asm("tanh.approx.f32 %0, %1;" : "=f"(y) : "f"(x));
    return y;
}

__device__ __forceinline__ uint2 f4_to_h4(float4 o) {
    uint32_t a, b;
    asm("cvt.rn.f16x2.f32 %0, %1, %2;" : "=r"(a) : "f"(o.y), "f"(o.x));
    asm("cvt.rn.f16x2.f32 %0, %1, %2;" : "=r"(b) : "f"(o.w), "f"(o.z));
    return make_uint2(a, b);
}

#define MMA_F16(D, a0, a1, a2, a3, b0, b1)                                     \
    asm volatile("mma.sync.aligned.m16n8k16.row.col.f32.f16.f16.f32 "          \
                 "{%0,%1,%2,%3}, {%4,%5,%6,%7}, {%8,%9}, {%0,%1,%2,%3};"       \
                 : "+f"((D)[0]), "+f"((D)[1]), "+f"((D)[2]), "+f"((D)[3])      \
                 : "r"(a0), "r"(a1), "r"(a2), "r"(a3), "r"(b0), "r"(b1))

#define LDSM_X4(r0, r1, r2, r3, addr)                                          \
    asm volatile("ldmatrix.sync.aligned.m8n8.x4.shared.b16 {%0,%1,%2,%3}, [%4];" \
                 : "=r"(r0), "=r"(r1), "=r"(r2), "=r"(r3) : "r"(addr))

#define LDSM_X2(r0, r1, addr)                                                  \
    asm volatile("ldmatrix.sync.aligned.m8n8.x2.shared.b16 {%0,%1}, [%2];"     \
                 : "=r"(r0), "=r"(r1) : "r"(addr))

// ---------------- K0: zero output ----------------
__global__ void k_zero(float* __restrict__ out) {
    ((float4*)out)[threadIdx.x] = make_float4(0.f, 0.f, 0.f, 0.f);
}

// ---------------- K1: C0 = embed[Z] ----------------
__global__ __launch_bounds__(256) void k_init(const int* __restrict__ Z,
                                              const float* __restrict__ embed) {
    int idx = blockIdx.x * 256 + threadIdx.x;
    int v = idx >> 5, c4 = idx & 31;
    float4 val = ((const float4*)embed)[(size_t)Z[v] * 32 + c4];
    ((float4*)g_C[0])[idx] = val;
}

// ---------------- sort-by-dst pipeline (one-time) ----------------
__global__ __launch_bounds__(256) void k_clear() {
    int i = blockIdx.x * 256 + threadIdx.x;
    if (i < N_NODES) g_cnt[i] = 0;
}

__global__ __launch_bounds__(256) void k_hist(const int* __restrict__ edge_index) {
    int e = blockIdx.x * 256 + threadIdx.x;
    if (e < N_EDGES) atomicAdd(&g_cnt[edge_index[N_EDGES + e]], 1);
}

__global__ __launch_bounds__(1024) void k_scan() {
    __shared__ int sdata[1024];
    int t = threadIdx.x;
    const int PER = 20;
    int base = t * PER;
    int v[PER]; int s = 0;
#pragma unroll
    for (int j = 0; j < PER; j++) {
        int i = base + j;
        v[j] = (i < N_NODES) ? g_cnt[i] : 0;
        s += v[j];
    }
    sdata[t] = s;
    __syncthreads();
    for (int off = 1; off < 1024; off <<= 1) {
        int y = (t >= off) ? sdata[t - off] : 0;
        __syncthreads();
        sdata[t] += y;
        __syncthreads();
    }
    int run = sdata[t] - s;
#pragma unroll
    for (int j = 0; j < PER; j++) {
        int i = base + j;
        if (i < N_NODES) { g_off[i] = run; g_cur[i] = run; run += v[j]; }
    }
    if (t == 1023) g_off[N_NODES] = run;
}

__global__ __launch_bounds__(256) void k_scatter(const int* __restrict__ edge_index) {
    int e = blockIdx.x * 256 + threadIdx.x;
    if (e < N_EDGES) {
        int dst = edge_index[N_EDGES + e];
        int pos = atomicAdd(&g_cur[dst], 1);
        g_perm[pos] = e;
        g_srcp[pos] = edge_index[e];
        g_dstp[pos] = dst;
    }
}

__global__ __launch_bounds__(256) void k_wsplit(const float* __restrict__ fcW) {
    for (int i = blockIdx.x * 256 + threadIdx.x; i < BASIS * BASIS; i += gridDim.x * 256) {
        __half h = __float2half_rn(fcW[i]);
        g_Wh[i] = __half_as_ushort(h);
    }
}

// ---------------- K2: d_feat (dst-sorted, fp16) = edge_attr[perm]@dfW.T + dfb --
__global__ __launch_bounds__(256) void k_dfeat(const float* __restrict__ edge_attr,
                                               const float* __restrict__ dfW,
                                               const float* __restrict__ dfb) {
    extern __shared__ float sm[];
    float* sW = sm;                  // [128][64]
    float* sA = sm + 128 * 64;       // [64][68]
    float* sB = sA + 64 * 68;        // [128]
    int*   sPerm = (int*)(sB + 128); // [64]
    int t = threadIdx.x;
    int e0 = blockIdx.x * 64;

    if (t < 64) sPerm[t] = g_perm[e0 + t];
    __syncthreads();

    for (int i = t; i < 2048; i += 256)
        ((float4*)sW)[i] = ((const float4*)dfW)[i];
    if (t < 128) sB[t] = dfb[t];
    for (int i = t; i < 64 * 16; i += 256) {
        int e = i >> 4, g4 = i & 15;
        float4 v = ((const float4*)edge_attr)[(size_t)sPerm[e] * 16 + g4];
        *(float4*)&sA[e * 68 + g4 * 4] = v;
    }
    __syncthreads();

    int tx = t & 7, ty = t >> 3;
    float acc[8][4];
#pragma unroll
    for (int ii = 0; ii < 8; ii++)
#pragma unroll
        for (int jj = 0; jj < 4; jj++) acc[ii][jj] = 0.f;

#pragma unroll 4
    for (int k = 0; k < 64; k += 4) {
        float4 av[8], wv[4];
#pragma unroll
        for (int ii = 0; ii < 8; ii++) av[ii] = *(float4*)&sA[(tx + 8 * ii) * 68 + k];
#pragma unroll
        for (int jj = 0; jj < 4; jj++) wv[jj] = *(float4*)&sW[(ty * 4 + jj) * 64 + k];
#pragma unroll
        for (int ii = 0; ii < 8; ii++)
#pragma unroll
            for (int jj = 0; jj < 4; jj++) {
                acc[ii][jj] = fmaf(av[ii].x, wv[jj].x, acc[ii][jj]);
                acc[ii][jj] = fmaf(av[ii].y, wv[jj].y, acc[ii][jj]);
                acc[ii][jj] = fmaf(av[ii].z, wv[jj].z, acc[ii][jj]);
                acc[ii][jj] = fmaf(av[ii].w, wv[jj].w, acc[ii][jj]);
            }
    }
    float4 bb = *(float4*)&sB[ty * 4];
#pragma unroll
    for (int ii = 0; ii < 8; ii++) {
        float4 o = make_float4(acc[ii][0] + bb.x, acc[ii][1] + bb.y,
                               acc[ii][2] + bb.z, acc[ii][3] + bb.w);
        ((uint2*)g_dfeat16)[(size_t)(e0 + tx + 8 * ii) * 32 + ty] = f4_to_h4(o);
    }
}

// ---------------- K3: Cc(fp16) = C@cfW.T + cfb ; C2 = C ----------------
__global__ __launch_bounds__(256) void k_node(const float* __restrict__ cfW,
                                              const float* __restrict__ cfb,
                                              int sb) {
    extern __shared__ float sm[];
    float* sW = sm;                  // [128][128]
    float* sC = sm + 16384;          // [32][132]
    float* sBb = sC + 32 * 132;      // [128]
    const float* C = g_C[sb];
    float* C2 = g_C[sb ^ 1];
    int t = threadIdx.x, n0 = blockIdx.x * 32;

    for (int i = t; i < 4096; i += 256)
        ((float4*)sW)[i] = ((const float4*)cfW)[i];
    if (t < 128) sBb[t] = cfb[t];
    for (int i = t; i < 32 * 32; i += 256) {
        int n = i >> 5, c4 = i & 31;
        *(float4*)&sC[n * 132 + c4 * 4] = ((const float4*)C)[(size_t)(n0 + n) * 32 + c4];
    }
    __syncthreads();

    int tx = t & 7, ty = t >> 3;
    float acc[4][4];
#pragma unroll
    for (int ii = 0; ii < 4; ii++)
#pragma unroll
        for (int jj = 0; jj < 4; jj++) acc[ii][jj] = 0.f;

#pragma unroll 4
    for (int k = 0; k < 128; k += 4) {
        float4 cv[4], wv[4];
#pragma unroll
        for (int ii = 0; ii < 4; ii++) cv[ii] = *(float4*)&sC[(tx + 8 * ii) * 132 + k];
#pragma unroll
        for (int jj = 0; jj < 4; jj++) wv[jj] = *(float4*)&sW[(ty * 4 + jj) * 128 + k];
#pragma unroll
        for (int ii = 0; ii < 4; ii++)
#pragma unroll
            for (int jj = 0; jj < 4; jj++) {
                acc[ii][jj] = fmaf(cv[ii].x, wv[jj].x, acc[ii][jj]);
                acc[ii][jj] = fmaf(cv[ii].y, wv[jj].y, acc[ii][jj]);
                acc[ii][jj] = fmaf(cv[ii].z, wv[jj].z, acc[ii][jj]);
                acc[ii][jj] = fmaf(cv[ii].w, wv[jj].w, acc[ii][jj]);
            }
    }
    float4 bb = *(float4*)&sBb[ty * 4];
#pragma unroll
    for (int ii = 0; ii < 4; ii++) {
        float4 o = make_float4(acc[ii][0] + bb.x, acc[ii][1] + bb.y,
                               acc[ii][2] + bb.z, acc[ii][3] + bb.w);
        ((uint2*)g_Cch)[(size_t)(n0 + tx + 8 * ii) * 32 + ty] = f4_to_h4(o);
    }
    for (int i = t; i < 32 * 32; i += 256) {
        int n = i >> 5, c4 = i & 31;
        ((float4*)C2)[(size_t)(n0 + n) * 32 + c4] = *(float4*)&sC[n * 132 + c4 * 4];
    }
}

// ---------------- K4 (hot): m = tanh((Cc[srcp]*d_feat)@fcW.T); C2[dst] += m -----
// All-fp16 operands. TE=128, 512 thr (16 warps, 4m x 4n grid, acc[32]/warp),
// ~71.7 KB smem -> 2 blocks/SM = 32 warps/SM. Two-half output staging.
#define TE  128
#define PB  136   // fp16 row stride
#define POH 68    // f32 staging stride (64 cols + pad)
__global__ __launch_bounds__(512, 2) void k_edge(int db) {
    extern __shared__ char smraw[];
    uint16_t* sW  = (uint16_t*)smraw;                // [128][136] fp16
    uint16_t* sP  = sW + 128 * PB;                   // [128][136] fp16
    int*      sSrc = (int*)(sP + TE * PB);           // [128]
    int*      sDst = sSrc + TE;                      // [128]
    float*    sOut = (float*)sP;                     // [128][68] f32, aliases sP
    float* C2 = g_C[db];
    int t = threadIdx.x, e0 = blockIdx.x * TE;

    // ---- phase 1: stage fp16 W; load src/dst ----
    for (int i = t; i < 2048; i += 512) {            // uint4 = 8 fp16
        int n = i >> 4, k8 = i & 15;
        *(uint4*)&sW[n * PB + k8 * 8] = ((const uint4*)g_Wh)[i];
    }
    if (t < TE)          sSrc[t]      = g_srcp[e0 + t];
    else if (t < 2 * TE) sDst[t - TE] = g_dstp[e0 + (t - TE)];
    __syncthreads();

    // ---- phase 2: P = h2(Cc[src]) * h2(d_feat)  (all fp16) ----
    for (int i = t; i < TE * 32; i += 512) {
        int e = i >> 5, c4 = i & 31;
        uint2 d2 = ((const uint2*)g_dfeat16)[(size_t)(e0 + e) * 32 + c4];
        uint2 c2 = ((const uint2*)g_Cch)[(size_t)sSrc[e] * 32 + c4];
        __half2 pa = __hmul2(*(__half2*)&d2.x, *(__half2*)&c2.x);
        __half2 pb = __hmul2(*(__half2*)&d2.y, *(__half2*)&c2.y);
        *(uint2*)&sP[e * PB + c4 * 4] =
            make_uint2(*(uint32_t*)&pa, *(uint32_t*)&pb);
    }
    __syncthreads();

    // ---- phase 3: fp16 GEMM  D[128x128] = P @ W^T, 16 warps 4m x 4n (32x32) ----
    const int lane = t & 31, wid = t >> 5;
    const int mbase = (wid >> 2) * 32;               // {0,32,64,96}
    const int nbase = (wid & 3) * 32;                // {0,32,64,96}
    const int aoff = (mbase + (lane & 15)) * PB + ((lane & 16) ? 8 : 0);
    const int boff = (nbase + (lane & 7)) * PB + ((lane & 8) ? 8 : 0);
    const uint32_t sPA = (uint32_t)__cvta_generic_to_shared(sP);
    const uint32_t sWA = (uint32_t)__cvta_generic_to_shared(sW);

    float acc[32];                                   // [mt2][nt4][4]
#pragma unroll
    for (int i = 0; i < 32; i++) acc[i] = 0.f;

#pragma unroll
    for (int kt = 0; kt < 8; kt++) {
        uint32_t a[2][4];
#pragma unroll
        for (int mt = 0; mt < 2; mt++) {
            uint32_t off = (uint32_t)(aoff + mt * 16 * PB + kt * 16) * 2;
            LDSM_X4(a[mt][0], a[mt][1], a[mt][2], a[mt][3], sPA + off);
        }
#pragma unroll
        for (int nt = 0; nt < 4; nt++) {
            uint32_t off = (uint32_t)(boff + nt * 8 * PB + kt * 16) * 2;
            uint32_t b0, b1;
            LDSM_X2(b0, b1, sWA + off);
#pragma unroll
            for (int mt = 0; mt < 2; mt++) {
                float* D = acc + (mt * 4 + nt) * 4;
                MMA_F16(D, a[mt][0], a[mt][1], a[mt][2], a[mt][3], b0, b1);
            }
        }
    }
    __syncthreads();                                 // all sP reads done

    // ---- phases 4+5: two column halves; sOut aliases sP ----
    const int grp = lane >> 2, t4 = lane & 3;
#pragma unroll
    for (int half = 0; half < 2; half++) {
        if ((nbase >> 6) == half) {                  // 8 warps own these 64 cols
            int nb = nbase & 63;                     // {0,32}
#pragma unroll
            for (int mt = 0; mt < 2; mt++)
#pragma unroll
                for (int nt = 0; nt < 4; nt++) {
                    int m = mbase + mt * 16 + grp;
                    int n = nb + nt * 8 + 2 * t4;
                    const float* D = acc + (mt * 4 + nt) * 4;
                    *(float2*)&sOut[m * POH + n] =
                        make_float2(tanh_approx(D[0]), tanh_approx(D[1]));
                    *(float2*)&sOut[(m + 8) * POH + n] =
                        make_float2(tanh_approx(D[2]), tanh_approx(D[3]));
                }
        }
        __syncthreads();
        // run-aggregated scatter for this half (dst-sorted rows)
        {
            int c4 = t & 15;                         // float4 col within half
            int r0 = (t >> 4) * 4;                   // 32 strips x 4 rows
            float4 a4 = make_float4(0.f, 0.f, 0.f, 0.f);
            int cur = sDst[r0];
#pragma unroll
            for (int j = 0; j < 4; j++) {
                int r = r0 + j;
                int d = sDst[r];
                if (d != cur) {
                    float* ptr = C2 + (size_t)cur * BASIS + half * 64 + c4 * 4;
                    asm volatile("red.global.add.v4.f32 [%0], {%1,%2,%3,%4};"
                                 :: "l"(ptr), "f"(a4.x), "f"(a4.y), "f"(a4.z), "f"(a4.w)
                                 : "memory");
                    a4 = make_float4(0.f, 0.f, 0.f, 0.f);
                    cur = d;
                }
                float4 v = *(float4*)&sOut[r * POH + c4 * 4];
                a4.x += v.x; a4.y += v.y; a4.z += v.z; a4.w += v.w;
            }
            float* ptr = C2 + (size_t)cur * BASIS + half * 64 + c4 * 4;
            asm volatile("red.global.add.v4.f32 [%0], {%1,%2,%3,%4};"
                         :: "l"(ptr), "f"(a4.x), "f"(a4.y), "f"(a4.z), "f"(a4.w)
                         : "memory");
        }
        if (half == 0) __syncthreads();              // before overwriting sOut
    }
}

// ---------------- K5: readout + pool ----------------
__global__ __launch_bounds__(256) void k_readout(const float* __restrict__ r1W,
                                                 const float* __restrict__ r1b,
                                                 const float* __restrict__ r2W,
                                                 const float* __restrict__ r2b,
                                                 const int* __restrict__ batch,
                                                 float* __restrict__ out, int sb) {
    extern __shared__ float sm[];
    float* sW1 = sm;                   // [256][128]
    float* sC  = sW1 + 32768;          // [32][132]
    float* sW2 = sC + 32 * 132;        // [4][256]
    float* sB1 = sW2 + 1024;           // [256]
    float* sAcc = sB1 + 256;           // [32][4]
    int*   sBat = (int*)(sAcc + 128);  // [32]
    const float* C = g_C[sb];
    int t = threadIdx.x, n0 = blockIdx.x * 32;

    for (int i = t; i < 8192; i += 256)
        ((float4*)sW1)[i] = ((const float4*)r1W)[i];
    if (t < 256) ((float4*)sW2)[t] = ((const float4*)r2W)[t];
    sB1[t] = r1b[t];
    if (t < 128) sAcc[t] = 0.f;
    if (t < 32)  sBat[t] = batch[n0 + t];
    for (int i = t; i < 32 * 32; i += 256) {
        int n = i >> 5, c4 = i & 31;
        *(float4*)&sC[n * 132 + c4 * 4] = ((const float4*)C)[(size_t)(n0 + n) * 32 + c4];
    }
    __syncthreads();

    int tx = t & 7, ty = t >> 3;
    float acc[4][8];
#pragma unroll
    for (int ii = 0; ii < 4; ii++)
#pragma unroll
        for (int jj = 0; jj < 8; jj++) acc[ii][jj] = 0.f;

#pragma unroll 2
    for (int c = 0; c < 128; c += 4) {
        float4 cv[4], wv[8];
#pragma unroll
        for (int ii = 0; ii < 4; ii++) cv[ii] = *(float4*)&sC[(tx + 8 * ii) * 132 + c];
#pragma unroll
        for (int jj = 0; jj < 8; jj++) wv[jj] = *(float4*)&sW1[(ty * 8 + jj) * 128 + c];
#pragma unroll
        for (int ii = 0; ii < 4; ii++)
#pragma unroll
            for (int jj = 0; jj < 8; jj++) {
                acc[ii][jj] = fmaf(cv[ii].x, wv[jj].x, acc[ii][jj]);
                acc[ii][jj] = fmaf(cv[ii].y, wv[jj].y, acc[ii][jj]);
                acc[ii][jj] = fmaf(cv[ii].z, wv[jj].z, acc[ii][jj]);
                acc[ii][jj] = fmaf(cv[ii].w, wv[jj].w, acc[ii][jj]);
            }
    }
    float po[4][4];
#pragma unroll
    for (int ii = 0; ii < 4; ii++)
#pragma unroll
        for (int o = 0; o < 4; o++) po[ii][o] = (ty == 0) ? r2b[o] : 0.f;
#pragma unroll
    for (int ii = 0; ii < 4; ii++)
#pragma unroll
        for (int jj = 0; jj < 8; jj++) {
            float h = fast_tanh(acc[ii][jj] + sB1[ty * 8 + jj]);
#pragma unroll
            for (int o = 0; o < 4; o++)
                po[ii][o] = fmaf(h, sW2[o * 256 + ty * 8 + jj], po[ii][o]);
        }
#pragma unroll
    for (int ii = 0; ii < 4; ii++)
#pragma unroll
        for (int o = 0; o < 4; o++)
            atomicAdd(&sAcc[(tx + 8 * ii) * 4 + o], po[ii][o]);
    __syncthreads();
    if (t < 128) {
        int n = t >> 2, o = t & 3;
        atomicAdd(&out[(size_t)sBat[n] * 4 + o], sAcc[t]);
    }
}

// ---------------- launch ----------------
extern "C" void kernel_launch(void* const* d_in, const int* in_sizes, int n_in,
                              void* d_out, int out_size) {
    const int*   Z         = (const int*)d_in[0];
    const int*   edge_index= (const int*)d_in[1];
    const float* edge_attr = (const float*)d_in[2];
    const int*   batch     = (const int*)d_in[3];
    const float* embed     = (const float*)d_in[4];
    const float* cfW       = (const float*)d_in[5];
    const float* cfb       = (const float*)d_in[6];
    const float* dfW       = (const float*)d_in[7];
    const float* dfb       = (const float*)d_in[8];
    const float* fcW       = (const float*)d_in[9];
    const float* r1W       = (const float*)d_in[10];
    const float* r1b       = (const float*)d_in[11];
    const float* r2W       = (const float*)d_in[12];
    const float* r2b       = (const float*)d_in[13];
    float* out = (float*)d_out;

    const int smK2 = (128 * 64 + 64 * 68 + 128) * 4 + 64 * 4;             // ~51 KB
    const int smK3 = (16384 + 32 * 132 + 128) * 4;                        // ~83 KB
    const int smK4 = (128 * PB + TE * PB) * 2 + 2 * TE * 4;               // ~71.7 KB
    const int smK5 = (32768 + 32 * 132 + 1024 + 256 + 128) * 4 + 32 * 4;  // ~154 KB

    cudaFuncSetAttribute(k_dfeat,   cudaFuncAttributeMaxDynamicSharedMemorySize, smK2);
    cudaFuncSetAttribute(k_node,    cudaFuncAttributeMaxDynamicSharedMemorySize, smK3);
    cudaFuncSetAttribute(k_edge,    cudaFuncAttributeMaxDynamicSharedMemorySize, smK4);
    cudaFuncSetAttribute(k_readout, cudaFuncAttributeMaxDynamicSharedMemorySize, smK5);

    k_zero<<<1, 256>>>(out);
    k_init<<<(N_NODES * 32) / 256, 256>>>(Z, embed);

    // one-time edge sort by dst + W fp16 conversion
    k_clear<<<(N_NODES + 255) / 256, 256>>>();
    k_hist<<<(N_EDGES + 255) / 256, 256>>>(edge_index);
    k_scan<<<1, 1024>>>();
    k_scatter<<<(N_EDGES + 255) / 256, 256>>>(edge_index);
    k_wsplit<<<64, 256>>>(fcW);

    k_dfeat<<<N_EDGES / 64, 256, smK2>>>(edge_attr, dfW, dfb);

    int sb = 0;
    for (int it = 0; it < 3; it++) {
        k_node<<<N_NODES / 32, 256, smK3>>>(cfW, cfb, sb);
        k_edge<<<N_EDGES / TE, 512, smK4>>>(sb ^ 1);
        sb ^= 1;
    }
    k_readout<<<N_NODES / 32, 256, smK5>>>(r1W, r1b, r2W, r2b, batch, out, sb);
}

// round 17
// speedup vs baseline: 1.3590x; 1.1383x over previous
#include <cuda_runtime.h>
#include <cuda_bf16.h>
#include <cuda_fp16.h>
#include <cstdint>

#define N_NODES   20000
#define N_EDGES   640000
#define BASIS     128
#define NUM_GAUSS 64
#define HIDDEN    256
#define NUM_GRAPHS 256
#define NTILE     5000
#define NBLK      296

// ---------------- scratch (device globals) ----------------
__device__ uint16_t g_dfeat16[(size_t)N_EDGES * BASIS];
__device__ float    g_C[2][(size_t)N_NODES * BASIS];
__device__ uint16_t g_Cch[(size_t)N_NODES * BASIS];
__device__ uint16_t g_Wh[BASIS * BASIS];
__device__ int      g_perm[N_EDGES];
__device__ int      g_srcp[N_EDGES];
__device__ int      g_dstp[N_EDGES];
__device__ int      g_cnt[N_NODES];
__device__ int      g_off[N_NODES + 1];
__device__ int      g_cur[N_NODES];

__device__ __forceinline__ float fast_tanh(float x) {
    float xc = fminf(fmaxf(x, -9.0f), 9.0f);
    float e  = __expf(2.0f * xc);
    return __fdividef(e - 1.0f, e + 1.0f);
}

__device__ __forceinline__ float tanh_approx(float x) {
    float y;
    asm("tanh.approx.f32 %0, %1;" : "=f"(y) : "f"(x));
    return y;
}

__device__ __forceinline__ uint2 f4_to_h4(float4 o) {
    uint32_t a, b;
    asm("cvt.rn.f16x2.f32 %0, %1, %2;" : "=r"(a) : "f"(o.y), "f"(o.x));
    asm("cvt.rn.f16x2.f32 %0, %1, %2;" : "=r"(b) : "f"(o.w), "f"(o.z));
    return make_uint2(a, b);
}

#define MMA_F16(D, a0, a1, a2, a3, b0, b1)                                     \
    asm volatile("mma.sync.aligned.m16n8k16.row.col.f32.f16.f16.f32 "          \
                 "{%0,%1,%2,%3}, {%4,%5,%6,%7}, {%8,%9}, {%0,%1,%2,%3};"       \
                 : "+f"((D)[0]), "+f"((D)[1]), "+f"((D)[2]), "+f"((D)[3])      \
                 : "r"(a0), "r"(a1), "r"(a2), "r"(a3), "r"(b0), "r"(b1))

#define LDSM_X4(r0, r1, r2, r3, addr)                                          \
    asm volatile("ldmatrix.sync.aligned.m8n8.x4.shared.b16 {%0,%1,%2,%3}, [%4];" \
                 : "=r"(r0), "=r"(r1), "=r"(r2), "=r"(r3) : "r"(addr))

#define LDSM_X2(r0, r1, addr)                                                  \
    asm volatile("ldmatrix.sync.aligned.m8n8.x2.shared.b16 {%0,%1}, [%2];"     \
                 : "=r"(r0), "=r"(r1) : "r"(addr))

#define CP_ASYNC16(saddr, gptr)                                                \
    asm volatile("cp.async.cg.shared.global [%0], [%1], 16;"                   \
                 :: "r"(saddr), "l"(gptr))
#define CP_COMMIT() asm volatile("cp.async.commit_group;" ::: "memory")
#define CP_WAIT0()  asm volatile("cp.async.wait_group 0;" ::: "memory")

// ---------------- K0 ----------------
__global__ void k_zero(float* __restrict__ out) {
    ((float4*)out)[threadIdx.x] = make_float4(0.f, 0.f, 0.f, 0.f);
}

// ---------------- K1 ----------------
__global__ __launch_bounds__(256) void k_init(const int* __restrict__ Z,
                                              const float* __restrict__ embed) {
    int idx = blockIdx.x * 256 + threadIdx.x;
    int v = idx >> 5, c4 = idx & 31;
    float4 val = ((const float4*)embed)[(size_t)Z[v] * 32 + c4];
    ((float4*)g_C[0])[idx] = val;
}

// ---------------- sort-by-dst pipeline ----------------
__global__ __launch_bounds__(256) void k_clear() {
    int i = blockIdx.x * 256 + threadIdx.x;
    if (i < N_NODES) g_cnt[i] = 0;
}

__global__ __launch_bounds__(256) void k_hist(const int* __restrict__ edge_index) {
    int e = blockIdx.x * 256 + threadIdx.x;
    if (e < N_EDGES) atomicAdd(&g_cnt[edge_index[N_EDGES + e]], 1);
}

__global__ __launch_bounds__(1024) void k_scan() {
    __shared__ int sdata[1024];
    int t = threadIdx.x;
    const int PER = 20;
    int base = t * PER;
    int v[PER]; int s = 0;
#pragma unroll
    for (int j = 0; j < PER; j++) {
        int i = base + j;
        v[j] = (i < N_NODES) ? g_cnt[i] : 0;
        s += v[j];
    }
    sdata[t] = s;
    __syncthreads();
    for (int off = 1; off < 1024; off <<= 1) {
        int y = (t >= off) ? sdata[t - off] : 0;
        __syncthreads();
        sdata[t] += y;
        __syncthreads();
    }
    int run = sdata[t] - s;
#pragma unroll
    for (int j = 0; j < PER; j++) {
        int i = base + j;
        if (i < N_NODES) { g_off[i] = run; g_cur[i] = run; run += v[j]; }
    }
    if (t == 1023) g_off[N_NODES] = run;
}

__global__ __launch_bounds__(256) void k_scatter(const int* __restrict__ edge_index) {
    int e = blockIdx.x * 256 + threadIdx.x;
    if (e < N_EDGES) {
        int dst = edge_index[N_EDGES + e];
        int pos = atomicAdd(&g_cur[dst], 1);
        g_perm[pos] = e;
        g_srcp[pos] = edge_index[e];
        g_dstp[pos] = dst;
    }
}

__global__ __launch_bounds__(256) void k_wsplit(const float* __restrict__ fcW) {
    for (int i = blockIdx.x * 256 + threadIdx.x; i < BASIS * BASIS; i += gridDim.x * 256) {
        __half h = __float2half_rn(fcW[i]);
        g_Wh[i] = __half_as_ushort(h);
    }
}

// ---------------- K2 ----------------
__global__ __launch_bounds__(256) void k_dfeat(const float* __restrict__ edge_attr,
                                               const float* __restrict__ dfW,
                                               const float* __restrict__ dfb) {
    extern __shared__ float sm[];
    float* sW = sm;
    float* sA = sm + 128 * 64;
    float* sB = sA + 64 * 68;
    int*   sPerm = (int*)(sB + 128);
    int t = threadIdx.x;
    int e0 = blockIdx.x * 64;

    if (t < 64) sPerm[t] = g_perm[e0 + t];
    __syncthreads();

    for (int i = t; i < 2048; i += 256)
        ((float4*)sW)[i] = ((const float4*)dfW)[i];
    if (t < 128) sB[t] = dfb[t];
    for (int i = t; i < 64 * 16; i += 256) {
        int e = i >> 4, g4 = i & 15;
        float4 v = ((const float4*)edge_attr)[(size_t)sPerm[e] * 16 + g4];
        *(float4*)&sA[e * 68 + g4 * 4] = v;
    }
    __syncthreads();

    int tx = t & 7, ty = t >> 3;
    float acc[8][4];
#pragma unroll
    for (int ii = 0; ii < 8; ii++)
#pragma unroll
        for (int jj = 0; jj < 4; jj++) acc[ii][jj] = 0.f;

#pragma unroll 4
    for (int k = 0; k < 64; k += 4) {
        float4 av[8], wv[4];
#pragma unroll
        for (int ii = 0; ii < 8; ii++) av[ii] = *(float4*)&sA[(tx + 8 * ii) * 68 + k];
#pragma unroll
        for (int jj = 0; jj < 4; jj++) wv[jj] = *(float4*)&sW[(ty * 4 + jj) * 64 + k];
#pragma unroll
        for (int ii = 0; ii < 8; ii++)
#pragma unroll
            for (int jj = 0; jj < 4; jj++) {
                acc[ii][jj] = fmaf(av[ii].x, wv[jj].x, acc[ii][jj]);
                acc[ii][jj] = fmaf(av[ii].y, wv[jj].y, acc[ii][jj]);
                acc[ii][jj] = fmaf(av[ii].z, wv[jj].z, acc[ii][jj]);
                acc[ii][jj] = fmaf(av[ii].w, wv[jj].w, acc[ii][jj]);
            }
    }
    float4 bb = *(float4*)&sB[ty * 4];
#pragma unroll
    for (int ii = 0; ii < 8; ii++) {
        float4 o = make_float4(acc[ii][0] + bb.x, acc[ii][1] + bb.y,
                               acc[ii][2] + bb.z, acc[ii][3] + bb.w);
        ((uint2*)g_dfeat16)[(size_t)(e0 + tx + 8 * ii) * 32 + ty] = f4_to_h4(o);
    }
}

// ---------------- K3 ----------------
__global__ __launch_bounds__(256) void k_node(const float* __restrict__ cfW,
                                              const float* __restrict__ cfb,
                                              int sb) {
    extern __shared__ float sm[];
    float* sW = sm;
    float* sC = sm + 16384;
    float* sBb = sC + 32 * 132;
    const float* C = g_C[sb];
    float* C2 = g_C[sb ^ 1];
    int t = threadIdx.x, n0 = blockIdx.x * 32;

    for (int i = t; i < 4096; i += 256)
        ((float4*)sW)[i] = ((const float4*)cfW)[i];
    if (t < 128) sBb[t] = cfb[t];
    for (int i = t; i < 32 * 32; i += 256) {
        int n = i >> 5, c4 = i & 31;
        *(float4*)&sC[n * 132 + c4 * 4] = ((const float4*)C)[(size_t)(n0 + n) * 32 + c4];
    }
    __syncthreads();

    int tx = t & 7, ty = t >> 3;
    float acc[4][4];
#pragma unroll
    for (int ii = 0; ii < 4; ii++)
#pragma unroll
        for (int jj = 0; jj < 4; jj++) acc[ii][jj] = 0.f;

#pragma unroll 4
    for (int k = 0; k < 128; k += 4) {
        float4 cv[4], wv[4];
#pragma unroll
        for (int ii = 0; ii < 4; ii++) cv[ii] = *(float4*)&sC[(tx + 8 * ii) * 132 + k];
#pragma unroll
        for (int jj = 0; jj < 4; jj++) wv[jj] = *(float4*)&sW[(ty * 4 + jj) * 128 + k];
#pragma unroll
        for (int ii = 0; ii < 4; ii++)
#pragma unroll
            for (int jj = 0; jj < 4; jj++) {
                acc[ii][jj] = fmaf(cv[ii].x, wv[jj].x, acc[ii][jj]);
                acc[ii][jj] = fmaf(cv[ii].y, wv[jj].y, acc[ii][jj]);
                acc[ii][jj] = fmaf(cv[ii].z, wv[jj].z, acc[ii][jj]);
                acc[ii][jj] = fmaf(cv[ii].w, wv[jj].w, acc[ii][jj]);
            }
    }
    float4 bb = *(float4*)&sBb[ty * 4];
#pragma unroll
    for (int ii = 0; ii < 4; ii++) {
        float4 o = make_float4(acc[ii][0] + bb.x, acc[ii][1] + bb.y,
                               acc[ii][2] + bb.z, acc[ii][3] + bb.w);
        ((uint2*)g_Cch)[(size_t)(n0 + tx + 8 * ii) * 32 + ty] = f4_to_h4(o);
    }
    for (int i = t; i < 32 * 32; i += 256) {
        int n = i >> 5, c4 = i & 31;
        ((float4*)C2)[(size_t)(n0 + n) * 32 + c4] = *(float4*)&sC[n * 132 + c4 * 4];
    }
}

// ---------------- K4: persistent, cp.async-pipelined edge kernel ----------------
#define TE  128
#define PB  136
#define POH 68
__global__ __launch_bounds__(512, 2) void k_edge(int db) {
    extern __shared__ char smraw[];
    uint16_t* sW   = (uint16_t*)smraw;                   // [128][136]  34816 B
    uint16_t* sP   = sW + 128 * PB;                      // [128][136]  34816 B
    uint16_t* sD   = sP + 128 * PB;                      // [128][128]  32768 B
    int*      sIdx = (int*)(sD + 128 * 128);             // [2][256]     2048 B
    float*    sOut = (float*)sP;                         // [128][68] f32 alias
    float* C2 = g_C[db];
    int t = threadIdx.x;
    const uint32_t sDA   = (uint32_t)__cvta_generic_to_shared(sD);
    const uint32_t sIdxA = (uint32_t)__cvta_generic_to_shared(sIdx);

    // stage W once per block
    for (int i = t; i < 2048; i += 512) {
        int n = i >> 4, k8 = i & 15;
        *(uint4*)&sW[n * PB + k8 * 8] = ((const uint4*)g_Wh)[i];
    }

    // prefetch tile 0
    int ib = 0;
    {
        int e0 = blockIdx.x * TE;
        const char* gD = (const char*)(g_dfeat16 + (size_t)e0 * BASIS);
        for (int c = t; c < 2048; c += 512)
            CP_ASYNC16(sDA + c * 16, gD + (size_t)c * 16);
        if (t < 32)
            CP_ASYNC16(sIdxA + t * 16, (const char*)(g_srcp + e0) + t * 16);
        else if (t < 64)
            CP_ASYNC16(sIdxA + 512 + (t - 32) * 16, (const char*)(g_dstp + e0) + (t - 32) * 16);
        CP_COMMIT();
    }

    const int lane = t & 31, wid = t >> 5;
    const int mbase = (wid >> 2) * 32;
    const int nbase = (wid & 3) * 32;
    const int aoff = (mbase + (lane & 15)) * PB + ((lane & 16) ? 8 : 0);
    const int boff = (nbase + (lane & 7)) * PB + ((lane & 8) ? 8 : 0);
    const uint32_t sPA = (uint32_t)__cvta_generic_to_shared(sP);
    const uint32_t sWA = (uint32_t)__cvta_generic_to_shared(sW);
    const int grp = lane >> 2, t4 = lane & 3;

    for (int tile = blockIdx.x; tile < NTILE; tile += NBLK) {
        const int* sSrc = sIdx + ib * 256;
        const int* sDst = sSrc + 128;

        CP_WAIT0();
        __syncthreads();                                 // sD/sIdx[ib] ready; sP free

        // phase 2: P = h2(Cc[src]) * h2(dfeat)
        for (int i = t; i < TE * 32; i += 512) {
            int e = i >> 5, c4 = i & 31;
            uint2 d2 = *(uint2*)&sD[e * 128 + c4 * 4];
            uint2 c2 = ((const uint2*)g_Cch)[(size_t)sSrc[e] * 32 + c4];
            __half2 pa = __hmul2(*(__half2*)&d2.x, *(__half2*)&c2.x);
            __half2 pb = __hmul2(*(__half2*)&d2.y, *(__half2*)&c2.y);
            *(uint2*)&sP[e * PB + c4 * 4] =
                make_uint2(*(uint32_t*)&pa, *(uint32_t*)&pb);
        }
        __syncthreads();                                 // sD consumed, sP built

        // prefetch next tile (overlaps GEMM/tanh/scatter)
        int next = tile + NBLK;
        if (next < NTILE) {
            int ne0 = next * TE;
            const char* gD = (const char*)(g_dfeat16 + (size_t)ne0 * BASIS);
            for (int c = t; c < 2048; c += 512)
                CP_ASYNC16(sDA + c * 16, gD + (size_t)c * 16);
            uint32_t ibN = (uint32_t)(ib ^ 1) * 1024;
            if (t < 32)
                CP_ASYNC16(sIdxA + ibN + t * 16, (const char*)(g_srcp + ne0) + t * 16);
            else if (t < 64)
                CP_ASYNC16(sIdxA + ibN + 512 + (t - 32) * 16, (const char*)(g_dstp + ne0) + (t - 32) * 16);
            CP_COMMIT();
        }

        // phase 3: fp16 GEMM D[128x128] = P @ W^T (16 warps, 32x32 tiles)
        float acc[32];
#pragma unroll
        for (int i = 0; i < 32; i++) acc[i] = 0.f;

#pragma unroll
        for (int kt = 0; kt < 8; kt++) {
            uint32_t a[2][4];
#pragma unroll
            for (int mt = 0; mt < 2; mt++) {
                uint32_t off = (uint32_t)(aoff + mt * 16 * PB + kt * 16) * 2;
                LDSM_X4(a[mt][0], a[mt][1], a[mt][2], a[mt][3], sPA + off);
            }
#pragma unroll
            for (int nt = 0; nt < 4; nt++) {
                uint32_t off = (uint32_t)(boff + nt * 8 * PB + kt * 16) * 2;
                uint32_t b0, b1;
                LDSM_X2(b0, b1, sWA + off);
#pragma unroll
                for (int mt = 0; mt < 2; mt++) {
                    float* D = acc + (mt * 4 + nt) * 4;
                    MMA_F16(D, a[mt][0], a[mt][1], a[mt][2], a[mt][3], b0, b1);
                }
            }
        }
        __syncthreads();                                 // sP reads done

        // phases 4+5: two 64-col halves (sOut aliases sP)
#pragma unroll
        for (int half = 0; half < 2; half++) {
            if ((nbase >> 6) == half) {                  // 8 warps own these cols
                int nb = nbase & 63;
#pragma unroll
                for (int mt = 0; mt < 2; mt++)
#pragma unroll
                    for (int nt = 0; nt < 4; nt++) {
                        int m = mbase + mt * 16 + grp;
                        int n = nb + nt * 8 + 2 * t4;
                        const float* D = acc + (mt * 4 + nt) * 4;
                        *(float2*)&sOut[m * POH + n] =
                            make_float2(tanh_approx(D[0]), tanh_approx(D[1]));
                        *(float2*)&sOut[(m + 8) * POH + n] =
                            make_float2(tanh_approx(D[2]), tanh_approx(D[3]));
                    }
            }
            __syncthreads();
            {
                int c4 = t & 15;
                int r0 = (t >> 4) * 4;                   // 32 strips x 4 rows
                float4 a4 = make_float4(0.f, 0.f, 0.f, 0.f);
                int cur = sDst[r0];
#pragma unroll
                for (int j = 0; j < 4; j++) {
                    int r = r0 + j;
                    int d = sDst[r];
                    if (d != cur) {
                        float* ptr = C2 + (size_t)cur * BASIS + half * 64 + c4 * 4;
                        asm volatile("red.global.add.v4.f32 [%0], {%1,%2,%3,%4};"
                                     :: "l"(ptr), "f"(a4.x), "f"(a4.y), "f"(a4.z), "f"(a4.w)
                                     : "memory");
                        a4 = make_float4(0.f, 0.f, 0.f, 0.f);
                        cur = d;
                    }
                    float4 v = *(float4*)&sOut[r * POH + c4 * 4];
                    a4.x += v.x; a4.y += v.y; a4.z += v.z; a4.w += v.w;
                }
                float* ptr = C2 + (size_t)cur * BASIS + half * 64 + c4 * 4;
                asm volatile("red.global.add.v4.f32 [%0], {%1,%2,%3,%4};"
                             :: "l"(ptr), "f"(a4.x), "f"(a4.y), "f"(a4.z), "f"(a4.w)
                             : "memory");
            }
            __syncthreads();                             // before next half / next tile
        }
        ib ^= 1;
    }
}

// ---------------- K5: readout + pool ----------------
__global__ __launch_bounds__(256) void k_readout(const float* __restrict__ r1W,
                                                 const float* __restrict__ r1b,
                                                 const float* __restrict__ r2W,
                                                 const float* __restrict__ r2b,
                                                 const int* __restrict__ batch,
                                                 float* __restrict__ out, int sb) {
    extern __shared__ float sm[];
    float* sW1 = sm;
    float* sC  = sW1 + 32768;
    float* sW2 = sC + 32 * 132;
    float* sB1 = sW2 + 1024;
    float* sAcc = sB1 + 256;
    int*   sBat = (int*)(sAcc + 128);
    const float* C = g_C[sb];
    int t = threadIdx.x, n0 = blockIdx.x * 32;

    for (int i = t; i < 8192; i += 256)
        ((float4*)sW1)[i] = ((const float4*)r1W)[i];
    if (t < 256) ((float4*)sW2)[t] = ((const float4*)r2W)[t];
    sB1[t] = r1b[t];
    if (t < 128) sAcc[t] = 0.f;
    if (t < 32)  sBat[t] = batch[n0 + t];
    for (int i = t; i < 32 * 32; i += 256) {
        int n = i >> 5, c4 = i & 31;
        *(float4*)&sC[n * 132 + c4 * 4] = ((const float4*)C)[(size_t)(n0 + n) * 32 + c4];
    }
    __syncthreads();

    int tx = t & 7, ty = t >> 3;
    float acc[4][8];
#pragma unroll
    for (int ii = 0; ii < 4; ii++)
#pragma unroll
        for (int jj = 0; jj < 8; jj++) acc[ii][jj] = 0.f;

#pragma unroll 2
    for (int c = 0; c < 128; c += 4) {
        float4 cv[4], wv[8];
#pragma unroll
        for (int ii = 0; ii < 4; ii++) cv[ii] = *(float4*)&sC[(tx + 8 * ii) * 132 + c];
#pragma unroll
        for (int jj = 0; jj < 8; jj++) wv[jj] = *(float4*)&sW1[(ty * 8 + jj) * 128 + c];
#pragma unroll
        for (int ii = 0; ii < 4; ii++)
#pragma unroll
            for (int jj = 0; jj < 8; jj++) {
                acc[ii][jj] = fmaf(cv[ii].x, wv[jj].x, acc[ii][jj]);
                acc[ii][jj] = fmaf(cv[ii].y, wv[jj].y, acc[ii][jj]);
                acc[ii][jj] = fmaf(cv[ii].z, wv[jj].z, acc[ii][jj]);
                acc[ii][jj] = fmaf(cv[ii].w, wv[jj].w, acc[ii][jj]);
            }
    }
    float po[4][4];
#pragma unroll
    for (int ii = 0; ii < 4; ii++)
#pragma unroll
        for (int o = 0; o < 4; o++) po[ii][o] = (ty == 0) ? r2b[o] : 0.f;
#pragma unroll
    for (int ii = 0; ii < 4; ii++)
#pragma unroll
        for (int jj = 0; jj < 8; jj++) {
            float h = fast_tanh(acc[ii][jj] + sB1[ty * 8 + jj]);
#pragma unroll
            for (int o = 0; o < 4; o++)
                po[ii][o] = fmaf(h, sW2[o * 256 + ty * 8 + jj], po[ii][o]);
        }
#pragma unroll
    for (int ii = 0; ii < 4; ii++)
#pragma unroll
        for (int o = 0; o < 4; o++)
            atomicAdd(&sAcc[(tx + 8 * ii) * 4 + o], po[ii][o]);
    __syncthreads();
    if (t < 128) {
        int n = t >> 2, o = t & 3;
        atomicAdd(&out[(size_t)sBat[n] * 4 + o], sAcc[t]);
    }
}

// ---------------- launch ----------------
extern "C" void kernel_launch(void* const* d_in, const int* in_sizes, int n_in,
                              void* d_out, int out_size) {
    const int*   Z         = (const int*)d_in[0];
    const int*   edge_index= (const int*)d_in[1];
    const float* edge_attr = (const float*)d_in[2];
    const int*   batch     = (const int*)d_in[3];
    const float* embed     = (const float*)d_in[4];
    const float* cfW       = (const float*)d_in[5];
    const float* cfb       = (const float*)d_in[6];
    const float* dfW       = (const float*)d_in[7];
    const float* dfb       = (const float*)d_in[8];
    const float* fcW       = (const float*)d_in[9];
    const float* r1W       = (const float*)d_in[10];
    const float* r1b       = (const float*)d_in[11];
    const float* r2W       = (const float*)d_in[12];
    const float* r2b       = (const float*)d_in[13];
    float* out = (float*)d_out;

    const int smK2 = (128 * 64 + 64 * 68 + 128) * 4 + 64 * 4;
    const int smK3 = (16384 + 32 * 132 + 128) * 4;
    const int smK4 = 128 * PB * 2 + 128 * PB * 2 + 128 * 128 * 2 + 2048;  // 104448
    const int smK5 = (32768 + 32 * 132 + 1024 + 256 + 128) * 4 + 32 * 4;

    cudaFuncSetAttribute(k_dfeat,   cudaFuncAttributeMaxDynamicSharedMemorySize, smK2);
    cudaFuncSetAttribute(k_node,    cudaFuncAttributeMaxDynamicSharedMemorySize, smK3);
    cudaFuncSetAttribute(k_edge,    cudaFuncAttributeMaxDynamicSharedMemorySize, smK4);
    cudaFuncSetAttribute(k_readout, cudaFuncAttributeMaxDynamicSharedMemorySize, smK5);

    k_zero<<<1, 256>>>(out);
    k_init<<<(N_NODES * 32) / 256, 256>>>(Z, embed);

    k_clear<<<(N_NODES + 255) / 256, 256>>>();
    k_hist<<<(N_EDGES + 255) / 256, 256>>>(edge_index);
    k_scan<<<1, 1024>>>();
    k_scatter<<<(N_EDGES + 255) / 256, 256>>>(edge_index);
    k_wsplit<<<64, 256>>>(fcW);

    k_dfeat<<<N_EDGES / 64, 256, smK2>>>(edge_attr, dfW, dfb);

    int sb = 0;
    for (int it = 0; it < 3; it++) {
        k_node<<<N_NODES / 32, 256, smK3>>>(cfW, cfb, sb);
        k_edge<<<NBLK, 512, smK4>>>(sb ^ 1);
        sb ^= 1;
    }
    k_readout<<<N_NODES / 32, 256, smK5>>>(r1W, r1b, r2W, r2b, batch, out, sb);
}